// round 4
// baseline (speedup 1.0000x reference)
#include <cuda_runtime.h>
#include <math.h>

#define NNODES 10000
#define NEDGES 100000
#define NH     3
#define CH     1024
#define HC     3072          /* NH*CH */
#define ET     110000        /* NEDGES + NNODES self loops */
#define NCLS   460
#define FIN    1024

// ------------------------- scratch (device globals, no allocs) -------------
__device__ float g_xl[(size_t)NNODES * HC];      // x @ Wl + bl
__device__ float g_xr[(size_t)NNODES * HC];      // x @ Wr + br
__device__ float g_score[(size_t)ET * NH];       // raw attention scores per edge
__device__ float g_hmean[(size_t)NNODES * CH];   // head-mean aggregate + bias
__device__ int   g_count[NNODES];
__device__ int   g_rowstart[NNODES + 1];
__device__ int   g_cursor[NNODES];
__device__ int   g_csr[ET];

// ------------------------- SGEMM: C = A@B + bias ---------------------------
// BM=BN=128, BK=8, 8x8 per thread, 256 threads.
// mode 0: A=Aext(x), C=g_xl ; mode 1: A=Aext(x), C=g_xr ; mode 2: A=g_hmean, C=Cext
__global__ __launch_bounds__(256) void sgemm_bias(
    const float* __restrict__ Aext, const float* __restrict__ B,
    const float* __restrict__ bias, float* __restrict__ Cext,
    int M, int Nn, int K, int mode)
{
    const float* A = (mode == 2) ? g_hmean : Aext;
    float* C = (mode == 0) ? g_xl : ((mode == 1) ? g_xr : Cext);

    __shared__ float As[8][128];
    __shared__ float Bs[8][128];
    const int tid = threadIdx.x;
    const int tx  = tid & 15;   // N direction (16 threads)
    const int ty  = tid >> 4;   // M direction (16 threads)
    const int rowBase = blockIdx.y * 128;
    const int colBase = blockIdx.x * 128;

    const int aRow = tid >> 1;         // 0..127
    const int aCol = (tid & 1) * 4;    // 0 or 4
    const int bRow = tid >> 5;         // 0..7
    const int bCol = (tid & 31) * 4;   // 0..124

    float acc[8][8];
#pragma unroll
    for (int i = 0; i < 8; i++)
#pragma unroll
        for (int j = 0; j < 8; j++) acc[i][j] = 0.f;

    for (int k0 = 0; k0 < K; k0 += 8) {
        float4 av = make_float4(0.f, 0.f, 0.f, 0.f);
        int ar = rowBase + aRow;
        if (ar < M) av = *(const float4*)(A + (size_t)ar * K + k0 + aCol);
        As[aCol + 0][aRow] = av.x;
        As[aCol + 1][aRow] = av.y;
        As[aCol + 2][aRow] = av.z;
        As[aCol + 3][aRow] = av.w;

        float4 bv = make_float4(0.f, 0.f, 0.f, 0.f);
        int bc = colBase + bCol;
        if (bc < Nn)  // Nn is a multiple of 4 here (3072, 460)
            bv = *(const float4*)(B + (size_t)(k0 + bRow) * Nn + bc);
        *(float4*)&Bs[bRow][bCol] = bv;

        __syncthreads();
#pragma unroll
        for (int kk = 0; kk < 8; kk++) {
            float aR[8], bR[8];
#pragma unroll
            for (int i = 0; i < 8; i++) aR[i] = As[kk][ty * 8 + i];
#pragma unroll
            for (int j = 0; j < 8; j++) bR[j] = Bs[kk][tx * 8 + j];
#pragma unroll
            for (int i = 0; i < 8; i++)
#pragma unroll
                for (int j = 0; j < 8; j++) acc[i][j] += aR[i] * bR[j];
        }
        __syncthreads();
    }

#pragma unroll
    for (int i = 0; i < 8; i++) {
        int r = rowBase + ty * 8 + i;
        if (r >= M) continue;
#pragma unroll
        for (int j = 0; j < 8; j += 4) {
            int c = colBase + tx * 8 + j;
            if (c < Nn) {
                float4 o;
                o.x = acc[i][j + 0] + bias[c + 0];
                o.y = acc[i][j + 1] + bias[c + 1];
                o.z = acc[i][j + 2] + bias[c + 2];
                o.w = acc[i][j + 3] + bias[c + 3];
                *(float4*)(C + (size_t)r * Nn + c) = o;
            }
        }
    }
}

// ------------------------- edge scores (one warp per edge) -----------------
__device__ __forceinline__ float lrelu(float v) { return v > 0.f ? v : 0.2f * v; }

__global__ __launch_bounds__(256) void edge_scores(
    const int* __restrict__ ei, const float* __restrict__ att)
{
    int warp = blockIdx.x * 8 + (threadIdx.x >> 5);
    int lane = threadIdx.x & 31;
    if (warp >= ET) return;
    int src, dst;
    if (warp < NEDGES) {
        src = ei[2 * warp];
        dst = ei[2 * warp + 1];
    } else {
        src = dst = warp - NEDGES;
    }
    const float4* xls = (const float4*)(g_xl + (size_t)src * HC);
    const float4* xrs = (const float4*)(g_xr + (size_t)dst * HC);
    const float4* at4 = (const float4*)att;

    float s[NH];
#pragma unroll
    for (int h = 0; h < NH; h++) {
        float acc = 0.f;
        for (int i = lane; i < 256; i += 32) {
            float4 a = xls[h * 256 + i];
            float4 b = xrs[h * 256 + i];
            float4 w = at4[h * 256 + i];
            acc += lrelu(a.x + b.x) * w.x;
            acc += lrelu(a.y + b.y) * w.y;
            acc += lrelu(a.z + b.z) * w.z;
            acc += lrelu(a.w + b.w) * w.w;
        }
#pragma unroll
        for (int off = 16; off; off >>= 1)
            acc += __shfl_xor_sync(0xFFFFFFFFu, acc, off);
        s[h] = acc;
    }
    if (lane == 0) {
        g_score[(size_t)warp * NH + 0] = s[0];
        g_score[(size_t)warp * NH + 1] = s[1];
        g_score[(size_t)warp * NH + 2] = s[2];
    }
}

// ------------------------- CSR build ---------------------------------------
__global__ void k_zero_counts()
{
    int i = blockIdx.x * blockDim.x + threadIdx.x;
    if (i < NNODES) g_count[i] = 0;
}

__global__ void k_count(const int* __restrict__ ei)
{
    int e = blockIdx.x * blockDim.x + threadIdx.x;
    if (e >= ET) return;
    int dst = (e < NEDGES) ? ei[2 * e + 1] : (e - NEDGES);
    atomicAdd(&g_count[dst], 1);
}

__global__ __launch_bounds__(1024) void k_scan()
{
    __shared__ int sh[1024];
    __shared__ int carry;
    int tid = threadIdx.x;
    if (tid == 0) carry = 0;
    __syncthreads();
    for (int base = 0; base < NNODES; base += 1024) {
        int i = base + tid;
        int v = (i < NNODES) ? g_count[i] : 0;
        sh[tid] = v;
        __syncthreads();
        for (int off = 1; off < 1024; off <<= 1) {
            int t = (tid >= off) ? sh[tid - off] : 0;
            __syncthreads();
            sh[tid] += t;
            __syncthreads();
        }
        int excl = carry + sh[tid] - v;
        if (i < NNODES) { g_rowstart[i] = excl; g_cursor[i] = excl; }
        __syncthreads();
        if (tid == 1023) carry += sh[1023];
        __syncthreads();
    }
    if (tid == 0) g_rowstart[NNODES] = carry;
}

__global__ void k_scatter(const int* __restrict__ ei)
{
    int e = blockIdx.x * blockDim.x + threadIdx.x;
    if (e >= ET) return;
    int dst = (e < NEDGES) ? ei[2 * e + 1] : (e - NEDGES);
    int pos = atomicAdd(&g_cursor[dst], 1);
    g_csr[pos] = e;
}

// ------------------------- per-node softmax + aggregate --------------------
__global__ __launch_bounds__(128) void node_aggr(
    const int* __restrict__ ei, const float* __restrict__ bias)
{
    int node = blockIdx.x;
    int t = threadIdx.x;
    int beg = g_rowstart[node];
    int end = g_rowstart[node + 1];

    __shared__ float mx[NH];
    __shared__ float inv_den[NH];
    if (t < NH) {
        float m = -3.0e38f;
        for (int p = beg; p < end; p++) {
            float sc = g_score[(size_t)g_csr[p] * NH + t];
            m = fmaxf(m, sc);
        }
        float d = 0.f;
        for (int p = beg; p < end; p++) {
            d += expf(g_score[(size_t)g_csr[p] * NH + t] - m);
        }
        mx[t] = m;
        inv_den[t] = 1.0f / (d + 1e-16f);
    }
    __syncthreads();

    float4 acc[NH][2];
#pragma unroll
    for (int h = 0; h < NH; h++)
#pragma unroll
        for (int q = 0; q < 2; q++) acc[h][q] = make_float4(0.f, 0.f, 0.f, 0.f);

    for (int p = beg; p < end; p++) {
        int e = g_csr[p];
        int src = (e < NEDGES) ? ei[2 * e] : (e - NEDGES);
        const float4* xls = (const float4*)(g_xl + (size_t)src * HC);
        float al[NH];
#pragma unroll
        for (int h = 0; h < NH; h++)
            al[h] = expf(g_score[(size_t)e * NH + h] - mx[h]) * inv_den[h];
#pragma unroll
        for (int h = 0; h < NH; h++) {
#pragma unroll
            for (int q = 0; q < 2; q++) {
                float4 v = xls[h * 256 + t + 128 * q];
                acc[h][q].x += al[h] * v.x;
                acc[h][q].y += al[h] * v.y;
                acc[h][q].z += al[h] * v.z;
                acc[h][q].w += al[h] * v.w;
            }
        }
    }

    const float inv3 = 1.0f / 3.0f;
#pragma unroll
    for (int q = 0; q < 2; q++) {
        int f = t + 128 * q;
        float4 o;
        o.x = (acc[0][q].x + acc[1][q].x + acc[2][q].x) * inv3 + bias[4 * f + 0];
        o.y = (acc[0][q].y + acc[1][q].y + acc[2][q].y) * inv3 + bias[4 * f + 1];
        o.z = (acc[0][q].z + acc[1][q].z + acc[2][q].z) * inv3 + bias[4 * f + 2];
        o.w = (acc[0][q].w + acc[1][q].w + acc[2][q].w) * inv3 + bias[4 * f + 3];
        *(float4*)(g_hmean + (size_t)node * CH + 4 * f) = o;
    }
}

// ------------------------- pass-through copy (kernel, not memcpy) ----------
__global__ void k_copy4(const float4* __restrict__ src, float4* __restrict__ dst,
                        int n4)
{
    int i = blockIdx.x * blockDim.x + threadIdx.x;
    if (i < n4) dst[i] = src[i];
}

// ------------------------- launch ------------------------------------------
extern "C" void kernel_launch(void* const* d_in, const int* in_sizes, int n_in,
                              void* d_out, int out_size)
{
    const float* x    = (const float*)d_in[0];
    const int*   ei   = (const int*)d_in[1];        // int32 pairs (src, dst)
    const float* Wl   = (const float*)d_in[2];
    const float* bl   = (const float*)d_in[3];
    const float* Wr   = (const float*)d_in[4];
    const float* br   = (const float*)d_in[5];
    const float* att  = (const float*)d_in[6];
    const float* bias = (const float*)d_in[7];
    const float* Wfc  = (const float*)d_in[8];
    const float* bfc  = (const float*)d_in[9];
    const float* exps   = (const float*)d_in[10];
    const float* exps_c = (const float*)d_in[11];
    float* out = (float*)d_out;

    // projections: xl = x@Wl + bl, xr = x@Wr + br
    {
        dim3 grid((HC + 127) / 128, (NNODES + 127) / 128);
        sgemm_bias<<<grid, 256>>>(x, Wl, bl, nullptr, NNODES, HC, FIN, 0);
        sgemm_bias<<<grid, 256>>>(x, Wr, br, nullptr, NNODES, HC, FIN, 1);
    }

    // CSR by destination (single stream serializes the phases)
    k_zero_counts<<<(NNODES + 255) / 256, 256>>>();
    k_count<<<(ET + 255) / 256, 256>>>(ei);
    k_scan<<<1, 1024>>>();
    k_scatter<<<(ET + 255) / 256, 256>>>(ei);

    // raw attention scores, one warp per edge
    edge_scores<<<(ET + 7) / 8, 256>>>(ei, att);

    // per-node softmax + aggregation + head mean + bias
    node_aggr<<<NNODES, 128>>>(ei, bias);

    // fc readout: h = hmean @ Wfc + bfc, written directly to d_out
    {
        dim3 grid((NCLS + 127) / 128, (NNODES + 127) / 128);
        sgemm_bias<<<grid, 256>>>(nullptr, Wfc, bfc, out, NNODES, NCLS, FIN, 2);
    }

    // pass-through outputs (kernel copies; counts are divisible by 4)
    size_t hElems = (size_t)NNODES * NCLS;
    int n4a = in_sizes[10] / 4;
    int n4b = in_sizes[11] / 4;
    k_copy4<<<(n4a + 255) / 256, 256>>>((const float4*)exps,
                                        (float4*)(out + hElems), n4a);
    k_copy4<<<(n4b + 255) / 256, 256>>>((const float4*)exps_c,
                                        (float4*)(out + hElems + in_sizes[10]), n4b);
}

// round 7
// speedup vs baseline: 1.9420x; 1.9420x over previous
#include <cuda_runtime.h>
#include <cuda_bf16.h>
#include <math.h>
#include <stdint.h>

#define NNODES 10000
#define NEDGES 100000
#define NH     3
#define CH     1024
#define HC     3072          /* NH*CH */
#define ET     110000        /* NEDGES + NNODES self loops */
#define NCLS   460
#define FIN    1024

// ------------------------- scratch (device globals, no allocs) -------------
__device__ float g_xl[(size_t)NNODES * HC];
__device__ float g_xr[(size_t)NNODES * HC];
__device__ float g_score[(size_t)ET * NH];
__device__ float g_hmean[(size_t)NNODES * CH];
__device__ int   g_count[NNODES];
__device__ int   g_rowstart[NNODES + 1];
__device__ int   g_cursor[NNODES];
__device__ int   g_csr[ET];
// bf16 hi/lo splits
__device__ __nv_bfloat16 g_xhi[(size_t)NNODES * FIN];
__device__ __nv_bfloat16 g_xlo[(size_t)NNODES * FIN];
__device__ __nv_bfloat16 g_wlThi[(size_t)HC * FIN];   // Wl^T [N=HC][K=FIN]
__device__ __nv_bfloat16 g_wlTlo[(size_t)HC * FIN];
__device__ __nv_bfloat16 g_wrThi[(size_t)HC * FIN];
__device__ __nv_bfloat16 g_wrTlo[(size_t)HC * FIN];

// ------------------------- split/transpose prep -----------------------------
__global__ void x_split(const float* __restrict__ x)
{
    int i = blockIdx.x * blockDim.x + threadIdx.x;
    if (i >= NNODES * FIN) return;
    float v = x[i];
    __nv_bfloat16 hi = __float2bfloat16_rn(v);
    float lo = v - __bfloat162float(hi);
    g_xhi[i] = hi;
    g_xlo[i] = __float2bfloat16_rn(lo);
}

// W [K=FIN][N=HC] -> WT hi/lo [N][K]
__global__ __launch_bounds__(256) void w_splitT(
    const float* __restrict__ W, __nv_bfloat16* __restrict__ Thi,
    __nv_bfloat16* __restrict__ Tlo)
{
    __shared__ float tile[32][33];
    int tx = threadIdx.x & 31;
    int ty = threadIdx.x >> 5;   // 0..7
    int n0 = blockIdx.x * 32;
    int k0 = blockIdx.y * 32;
#pragma unroll
    for (int i = ty; i < 32; i += 8)
        tile[i][tx] = W[(size_t)(k0 + i) * HC + n0 + tx];
    __syncthreads();
#pragma unroll
    for (int i = ty; i < 32; i += 8) {
        float v = tile[tx][i];             // = W[k0+tx][n0+i]
        __nv_bfloat16 hi = __float2bfloat16_rn(v);
        float lo = v - __bfloat162float(hi);
        size_t o = (size_t)(n0 + i) * FIN + k0 + tx;
        Thi[o] = hi;
        Tlo[o] = __float2bfloat16_rn(lo);
    }
}

// ------------------------- HMMA bf16-split GEMM ------------------------------
// C[M,HC] = (Ahi+Alo)[M,K] @ (BThi+BTlo)[HC,K]^T + bias  (3-term split, fp32 acc)
// CTA tile 128x128, warp tile 64x32, K chunks of 32, cp.async double buffer.
#define KC       32
#define NCHUNK   (FIN / KC)        /* 32 */
#define STRIDE   20                /* uint32 per smem row (16 data + 4 pad) */
#define BUF_U32  (128 * STRIDE)    /* 2560 u32 = 10240 B */
#define OFF_AHI  0
#define OFF_ALO  (1 * BUF_U32)
#define OFF_BHI  (2 * BUF_U32)
#define OFF_BLO  (3 * BUF_U32)
#define STAGE_U32 (4 * BUF_U32)    /* 10240 u32 */
#define GEMM_SMEM (2 * STAGE_U32 * 4)   /* 81920 B */

__device__ __forceinline__ uint32_t smem_u32(const void* p) {
    uint32_t a;
    asm("{ .reg .u64 t; cvta.to.shared.u64 t, %1; cvt.u32.u64 %0, t; }"
        : "=r"(a) : "l"(p));
    return a;
}
__device__ __forceinline__ void cp16(uint32_t saddr, const void* g, int src_sz) {
    asm volatile("cp.async.cg.shared.global [%0], [%1], 16, %2;"
                 :: "r"(saddr), "l"(g), "r"(src_sz));
}
__device__ __forceinline__ void mma_bf16(float& c0, float& c1, float& c2, float& c3,
                                         uint32_t a0, uint32_t a1, uint32_t a2,
                                         uint32_t a3, uint32_t b0, uint32_t b1) {
    asm volatile(
        "mma.sync.aligned.m16n8k16.row.col.f32.bf16.bf16.f32 "
        "{%0,%1,%2,%3}, {%4,%5,%6,%7}, {%8,%9}, {%0,%1,%2,%3};"
        : "+f"(c0), "+f"(c1), "+f"(c2), "+f"(c3)
        : "r"(a0), "r"(a1), "r"(a2), "r"(a3), "r"(b0), "r"(b1));
}

__global__ __launch_bounds__(256) void gemm_mma(
    const __nv_bfloat16* __restrict__ Ahi, const __nv_bfloat16* __restrict__ Alo,
    const __nv_bfloat16* __restrict__ BThi, const __nv_bfloat16* __restrict__ BTlo,
    const float* __restrict__ bias, float* __restrict__ C, int M)
{
    extern __shared__ uint32_t smem[];
    const uint32_t sbase = smem_u32(smem);
    const int t = threadIdx.x;
    const int w = t >> 5;
    const int lane = t & 31;
    const int gid = lane >> 2;       // 0..7
    const int tg  = lane & 3;        // 0..3
    const int warpM = w & 1;         // 2-way M split (64 rows)
    const int warpN = w >> 1;        // 4-way N split (32 cols)
    const int rowBase = blockIdx.y * 128;
    const int colBase = blockIdx.x * 128;

    auto issue = [&](int c, int s) {
        const int k0 = c * KC;
        const uint32_t base = sbase + s * (STAGE_U32 * 4);
#pragma unroll
        for (int i = 0; i < 2; i++) {
            int idx = t + i * 256;       // 0..511
            int row = idx >> 2;
            int q   = idx & 3;
            uint32_t soff = (uint32_t)(row * STRIDE + q * 4) * 4;  // bytes
            int ar = rowBase + row;
            int ok = (ar < M) ? 16 : 0;
            int arc = (ar < M) ? ar : 0;
            size_t ga = (size_t)arc * FIN + k0 + q * 8;
            cp16(base + OFF_AHI * 4 + soff, Ahi + ga, ok);
            cp16(base + OFF_ALO * 4 + soff, Alo + ga, ok);
            size_t gb = (size_t)(colBase + row) * FIN + k0 + q * 8;
            cp16(base + OFF_BHI * 4 + soff, BThi + gb, 16);
            cp16(base + OFF_BLO * 4 + soff, BTlo + gb, 16);
        }
        asm volatile("cp.async.commit_group;");
    };

    float acc[4][4][4];   // [mt][nt][reg]
#pragma unroll
    for (int mt = 0; mt < 4; mt++)
#pragma unroll
        for (int nt = 0; nt < 4; nt++)
#pragma unroll
            for (int r = 0; r < 4; r++) acc[mt][nt][r] = 0.f;

    issue(0, 0);

    for (int c = 0; c < NCHUNK; c++) {
        if (c + 1 < NCHUNK) {
            issue(c + 1, (c + 1) & 1);
            asm volatile("cp.async.wait_group 1;");
        } else {
            asm volatile("cp.async.wait_group 0;");
        }
        __syncthreads();

        const uint32_t* sb = smem + (c & 1) * STAGE_U32;
        const uint32_t* As_hi = sb + OFF_AHI;
        const uint32_t* As_lo = sb + OFF_ALO;
        const uint32_t* Bs_hi = sb + OFF_BHI;
        const uint32_t* Bs_lo = sb + OFF_BLO;

#pragma unroll
        for (int ks = 0; ks < 2; ks++) {
            const int kk = ks * 8 + tg;
            uint32_t ah[4][4], al[4][4];
#pragma unroll
            for (int mt = 0; mt < 4; mt++) {
                int r0 = warpM * 64 + mt * 16 + gid;
                ah[mt][0] = As_hi[r0 * STRIDE + kk];
                ah[mt][1] = As_hi[(r0 + 8) * STRIDE + kk];
                ah[mt][2] = As_hi[r0 * STRIDE + kk + 4];
                ah[mt][3] = As_hi[(r0 + 8) * STRIDE + kk + 4];
                al[mt][0] = As_lo[r0 * STRIDE + kk];
                al[mt][1] = As_lo[(r0 + 8) * STRIDE + kk];
                al[mt][2] = As_lo[r0 * STRIDE + kk + 4];
                al[mt][3] = As_lo[(r0 + 8) * STRIDE + kk + 4];
            }
#pragma unroll
            for (int nt = 0; nt < 4; nt++) {
                int n0 = warpN * 32 + nt * 8 + gid;
                uint32_t bh0 = Bs_hi[n0 * STRIDE + kk];
                uint32_t bh1 = Bs_hi[n0 * STRIDE + kk + 4];
                uint32_t bl0 = Bs_lo[n0 * STRIDE + kk];
                uint32_t bl1 = Bs_lo[n0 * STRIDE + kk + 4];
#pragma unroll
                for (int mt = 0; mt < 4; mt++) {
                    float* cc = acc[mt][nt];
                    mma_bf16(cc[0], cc[1], cc[2], cc[3],
                             ah[mt][0], ah[mt][1], ah[mt][2], ah[mt][3], bh0, bh1);
                    mma_bf16(cc[0], cc[1], cc[2], cc[3],
                             ah[mt][0], ah[mt][1], ah[mt][2], ah[mt][3], bl0, bl1);
                    mma_bf16(cc[0], cc[1], cc[2], cc[3],
                             al[mt][0], al[mt][1], al[mt][2], al[mt][3], bh0, bh1);
                }
            }
        }
        __syncthreads();
    }

    // epilogue: direct gmem stores with bias
#pragma unroll
    for (int mt = 0; mt < 4; mt++) {
        int r0 = rowBase + warpM * 64 + mt * 16 + gid;
        int r1 = r0 + 8;
#pragma unroll
        for (int nt = 0; nt < 4; nt++) {
            int cb = colBase + warpN * 32 + nt * 8 + tg * 2;
            float b0 = bias[cb], b1 = bias[cb + 1];
            if (r0 < M) {
                float2 o = make_float2(acc[mt][nt][0] + b0, acc[mt][nt][1] + b1);
                *(float2*)(C + (size_t)r0 * HC + cb) = o;
            }
            if (r1 < M) {
                float2 o = make_float2(acc[mt][nt][2] + b0, acc[mt][nt][3] + b1);
                *(float2*)(C + (size_t)r1 * HC + cb) = o;
            }
        }
    }
}

// ------------------------- SIMT SGEMM for fc readout ------------------------
__global__ __launch_bounds__(256) void sgemm_bias(
    const float* __restrict__ B, const float* __restrict__ bias,
    float* __restrict__ C, int M, int Nn, int K)
{
    const float* A = g_hmean;
    __shared__ float As[8][128];
    __shared__ float Bs[8][128];
    const int tid = threadIdx.x;
    const int tx  = tid & 15;
    const int ty  = tid >> 4;
    const int rowBase = blockIdx.y * 128;
    const int colBase = blockIdx.x * 128;
    const int aRow = tid >> 1;
    const int aCol = (tid & 1) * 4;
    const int bRow = tid >> 5;
    const int bCol = (tid & 31) * 4;

    float acc[8][8];
#pragma unroll
    for (int i = 0; i < 8; i++)
#pragma unroll
        for (int j = 0; j < 8; j++) acc[i][j] = 0.f;

    for (int k0 = 0; k0 < K; k0 += 8) {
        float4 av = make_float4(0.f, 0.f, 0.f, 0.f);
        int ar = rowBase + aRow;
        if (ar < M) av = *(const float4*)(A + (size_t)ar * K + k0 + aCol);
        As[aCol + 0][aRow] = av.x;
        As[aCol + 1][aRow] = av.y;
        As[aCol + 2][aRow] = av.z;
        As[aCol + 3][aRow] = av.w;
        float4 bv = make_float4(0.f, 0.f, 0.f, 0.f);
        int bc = colBase + bCol;
        if (bc < Nn)
            bv = *(const float4*)(B + (size_t)(k0 + bRow) * Nn + bc);
        *(float4*)&Bs[bRow][bCol] = bv;
        __syncthreads();
#pragma unroll
        for (int kk = 0; kk < 8; kk++) {
            float aR[8], bR[8];
#pragma unroll
            for (int i = 0; i < 8; i++) aR[i] = As[kk][ty * 8 + i];
#pragma unroll
            for (int j = 0; j < 8; j++) bR[j] = Bs[kk][tx * 8 + j];
#pragma unroll
            for (int i = 0; i < 8; i++)
#pragma unroll
                for (int j = 0; j < 8; j++) acc[i][j] += aR[i] * bR[j];
        }
        __syncthreads();
    }
#pragma unroll
    for (int i = 0; i < 8; i++) {
        int r = rowBase + ty * 8 + i;
        if (r >= M) continue;
#pragma unroll
        for (int j = 0; j < 8; j += 4) {
            int c = colBase + tx * 8 + j;
            if (c < Nn) {
                float4 o;
                o.x = acc[i][j + 0] + bias[c + 0];
                o.y = acc[i][j + 1] + bias[c + 1];
                o.z = acc[i][j + 2] + bias[c + 2];
                o.w = acc[i][j + 3] + bias[c + 3];
                *(float4*)(C + (size_t)r * Nn + c) = o;
            }
        }
    }
}

// ------------------------- edge scores (one warp per edge) -----------------
__device__ __forceinline__ float lrelu(float v) { return v > 0.f ? v : 0.2f * v; }

__global__ __launch_bounds__(256) void edge_scores(
    const int* __restrict__ ei, const float* __restrict__ att)
{
    int warp = blockIdx.x * 8 + (threadIdx.x >> 5);
    int lane = threadIdx.x & 31;
    if (warp >= ET) return;
    int src, dst;
    if (warp < NEDGES) {
        src = ei[2 * warp];
        dst = ei[2 * warp + 1];
    } else {
        src = dst = warp - NEDGES;
    }
    const float4* xls = (const float4*)(g_xl + (size_t)src * HC);
    const float4* xrs = (const float4*)(g_xr + (size_t)dst * HC);
    const float4* at4 = (const float4*)att;

    float s[NH];
#pragma unroll
    for (int h = 0; h < NH; h++) {
        float acc = 0.f;
        for (int i = lane; i < 256; i += 32) {
            float4 a = xls[h * 256 + i];
            float4 b = xrs[h * 256 + i];
            float4 w = at4[h * 256 + i];
            acc += lrelu(a.x + b.x) * w.x;
            acc += lrelu(a.y + b.y) * w.y;
            acc += lrelu(a.z + b.z) * w.z;
            acc += lrelu(a.w + b.w) * w.w;
        }
#pragma unroll
        for (int off = 16; off; off >>= 1)
            acc += __shfl_xor_sync(0xFFFFFFFFu, acc, off);
        s[h] = acc;
    }
    if (lane == 0) {
        g_score[(size_t)warp * NH + 0] = s[0];
        g_score[(size_t)warp * NH + 1] = s[1];
        g_score[(size_t)warp * NH + 2] = s[2];
    }
}

// ------------------------- CSR build ---------------------------------------
__global__ void k_zero_counts()
{
    int i = blockIdx.x * blockDim.x + threadIdx.x;
    if (i < NNODES) g_count[i] = 0;
}
__global__ void k_count(const int* __restrict__ ei)
{
    int e = blockIdx.x * blockDim.x + threadIdx.x;
    if (e >= ET) return;
    int dst = (e < NEDGES) ? ei[2 * e + 1] : (e - NEDGES);
    atomicAdd(&g_count[dst], 1);
}
__global__ __launch_bounds__(1024) void k_scan()
{
    __shared__ int sh[1024];
    __shared__ int carry;
    int tid = threadIdx.x;
    if (tid == 0) carry = 0;
    __syncthreads();
    for (int base = 0; base < NNODES; base += 1024) {
        int i = base + tid;
        int v = (i < NNODES) ? g_count[i] : 0;
        sh[tid] = v;
        __syncthreads();
        for (int off = 1; off < 1024; off <<= 1) {
            int t = (tid >= off) ? sh[tid - off] : 0;
            __syncthreads();
            sh[tid] += t;
            __syncthreads();
        }
        int excl = carry + sh[tid] - v;
        if (i < NNODES) { g_rowstart[i] = excl; g_cursor[i] = excl; }
        __syncthreads();
        if (tid == 1023) carry += sh[1023];
        __syncthreads();
    }
    if (tid == 0) g_rowstart[NNODES] = carry;
}
__global__ void k_scatter(const int* __restrict__ ei)
{
    int e = blockIdx.x * blockDim.x + threadIdx.x;
    if (e >= ET) return;
    int dst = (e < NEDGES) ? ei[2 * e + 1] : (e - NEDGES);
    int pos = atomicAdd(&g_cursor[dst], 1);
    g_csr[pos] = e;
}

// ------------------------- per-node softmax + aggregate --------------------
__global__ __launch_bounds__(128) void node_aggr(
    const int* __restrict__ ei, const float* __restrict__ bias)
{
    int node = blockIdx.x;
    int t = threadIdx.x;
    int beg = g_rowstart[node];
    int end = g_rowstart[node + 1];

    __shared__ float mx[NH];
    __shared__ float inv_den[NH];
    if (t < NH) {
        float m = -3.0e38f;
        for (int p = beg; p < end; p++)
            m = fmaxf(m, g_score[(size_t)g_csr[p] * NH + t]);
        float d = 0.f;
        for (int p = beg; p < end; p++)
            d += expf(g_score[(size_t)g_csr[p] * NH + t] - m);
        mx[t] = m;
        inv_den[t] = 1.0f / (d + 1e-16f);
    }
    __syncthreads();

    float4 acc[NH][2];
#pragma unroll
    for (int h = 0; h < NH; h++)
#pragma unroll
        for (int q = 0; q < 2; q++) acc[h][q] = make_float4(0.f, 0.f, 0.f, 0.f);

    for (int p = beg; p < end; p++) {
        int e = g_csr[p];
        int src = (e < NEDGES) ? ei[2 * e] : (e - NEDGES);
        const float4* xls = (const float4*)(g_xl + (size_t)src * HC);
        float al[NH];
#pragma unroll
        for (int h = 0; h < NH; h++)
            al[h] = expf(g_score[(size_t)e * NH + h] - mx[h]) * inv_den[h];
#pragma unroll
        for (int h = 0; h < NH; h++) {
#pragma unroll
            for (int q = 0; q < 2; q++) {
                float4 v = xls[h * 256 + t + 128 * q];
                acc[h][q].x += al[h] * v.x;
                acc[h][q].y += al[h] * v.y;
                acc[h][q].z += al[h] * v.z;
                acc[h][q].w += al[h] * v.w;
            }
        }
    }

    const float inv3 = 1.0f / 3.0f;
#pragma unroll
    for (int q = 0; q < 2; q++) {
        int f = t + 128 * q;
        float4 o;
        o.x = (acc[0][q].x + acc[1][q].x + acc[2][q].x) * inv3 + bias[4 * f + 0];
        o.y = (acc[0][q].y + acc[1][q].y + acc[2][q].y) * inv3 + bias[4 * f + 1];
        o.z = (acc[0][q].z + acc[1][q].z + acc[2][q].z) * inv3 + bias[4 * f + 2];
        o.w = (acc[0][q].w + acc[1][q].w + acc[2][q].w) * inv3 + bias[4 * f + 3];
        *(float4*)(g_hmean + (size_t)node * CH + 4 * f) = o;
    }
}

// ------------------------- pass-through copy --------------------------------
__global__ void k_copy4(const float4* __restrict__ src, float4* __restrict__ dst,
                        int n4)
{
    int i = blockIdx.x * blockDim.x + threadIdx.x;
    if (i < n4) dst[i] = src[i];
}

// ------------------------- launch ------------------------------------------
extern "C" void kernel_launch(void* const* d_in, const int* in_sizes, int n_in,
                              void* d_out, int out_size)
{
    const float* x    = (const float*)d_in[0];
    const int*   ei   = (const int*)d_in[1];
    const float* Wl   = (const float*)d_in[2];
    const float* bl   = (const float*)d_in[3];
    const float* Wr   = (const float*)d_in[4];
    const float* br   = (const float*)d_in[5];
    const float* att  = (const float*)d_in[6];
    const float* bias = (const float*)d_in[7];
    const float* Wfc  = (const float*)d_in[8];
    const float* bfc  = (const float*)d_in[9];
    const float* exps   = (const float*)d_in[10];
    const float* exps_c = (const float*)d_in[11];
    float* out = (float*)d_out;

    cudaFuncSetAttribute(gemm_mma, cudaFuncAttributeMaxDynamicSharedMemorySize,
                         GEMM_SMEM);

    // Resolve DEVICE addresses of all device-global buffers used as kernel
    // args. Passing the symbol directly from host code hands the kernel the
    // host shadow address — which GB300's ATS silently dereferences to zeros.
    float *pxl, *pxr;
    __nv_bfloat16 *pxhi, *pxlo, *plThi, *plTlo, *prThi, *prTlo;
    cudaGetSymbolAddress((void**)&pxl,   g_xl);
    cudaGetSymbolAddress((void**)&pxr,   g_xr);
    cudaGetSymbolAddress((void**)&pxhi,  g_xhi);
    cudaGetSymbolAddress((void**)&pxlo,  g_xlo);
    cudaGetSymbolAddress((void**)&plThi, g_wlThi);
    cudaGetSymbolAddress((void**)&plTlo, g_wlTlo);
    cudaGetSymbolAddress((void**)&prThi, g_wrThi);
    cudaGetSymbolAddress((void**)&prTlo, g_wrTlo);

    // bf16 hi/lo splits of x and W^T
    x_split<<<(NNODES * FIN + 255) / 256, 256>>>(x);
    {
        dim3 grid(HC / 32, FIN / 32);
        w_splitT<<<grid, 256>>>(Wl, plThi, plTlo);
        w_splitT<<<grid, 256>>>(Wr, prThi, prTlo);
    }

    // projections on tensor cores (mma.sync bf16, 3-term split)
    {
        dim3 grid(HC / 128, (NNODES + 127) / 128);
        gemm_mma<<<grid, 256, GEMM_SMEM>>>(pxhi, pxlo, plThi, plTlo,
                                           bl, pxl, NNODES);
        gemm_mma<<<grid, 256, GEMM_SMEM>>>(pxhi, pxlo, prThi, prTlo,
                                           br, pxr, NNODES);
    }

    // CSR by destination
    k_zero_counts<<<(NNODES + 255) / 256, 256>>>();
    k_count<<<(ET + 255) / 256, 256>>>(ei);
    k_scan<<<1, 1024>>>();
    k_scatter<<<(ET + 255) / 256, 256>>>(ei);

    // raw attention scores
    edge_scores<<<(ET + 7) / 8, 256>>>(ei, att);

    // per-node softmax + aggregation + head mean + bias
    node_aggr<<<NNODES, 128>>>(ei, bias);

    // fc readout
    {
        dim3 grid((NCLS + 127) / 128, (NNODES + 127) / 128);
        sgemm_bias<<<grid, 256>>>(Wfc, bfc, out, NNODES, NCLS, FIN);
    }

    // pass-through outputs
    size_t hElems = (size_t)NNODES * NCLS;
    int n4a = in_sizes[10] / 4;
    int n4b = in_sizes[11] / 4;
    k_copy4<<<(n4a + 255) / 256, 256>>>((const float4*)exps,
                                        (float4*)(out + hElems), n4a);
    k_copy4<<<(n4b + 255) / 256, 256>>>((const float4*)exps_c,
                                        (float4*)(out + hElems + in_sizes[10]), n4b);
}

// round 8
// speedup vs baseline: 2.2241x; 1.1452x over previous
#include <cuda_runtime.h>
#include <cuda_bf16.h>
#include <math.h>
#include <stdint.h>

#define NNODES 10000
#define NEDGES 100000
#define NH     3
#define CH     1024
#define HC     3072          /* NH*CH */
#define ET     110000        /* NEDGES + NNODES self loops */
#define NCLS   460
#define FIN    1024

// ------------------------- scratch (device globals, no allocs) -------------
__device__ float g_xl[(size_t)NNODES * HC];
__device__ float g_xr[(size_t)NNODES * HC];
__device__ float g_hmean[(size_t)NNODES * CH];
__device__ int   g_count[NNODES];
__device__ int   g_rowstart[NNODES + 1];
__device__ int   g_cursor[NNODES];
__device__ int   g_csr[ET];                      // stores SRC node per slot
// bf16 hi/lo splits
__device__ __nv_bfloat16 g_xhi[(size_t)NNODES * FIN];
__device__ __nv_bfloat16 g_xlo[(size_t)NNODES * FIN];
__device__ __nv_bfloat16 g_wlThi[(size_t)HC * FIN];   // Wl^T [N=HC][K=FIN]
__device__ __nv_bfloat16 g_wlTlo[(size_t)HC * FIN];
__device__ __nv_bfloat16 g_wrThi[(size_t)HC * FIN];
__device__ __nv_bfloat16 g_wrTlo[(size_t)HC * FIN];

// ------------------------- split/transpose prep -----------------------------
__global__ void x_split(const float* __restrict__ x)
{
    int i = blockIdx.x * blockDim.x + threadIdx.x;
    if (i >= NNODES * FIN) return;
    float v = x[i];
    __nv_bfloat16 hi = __float2bfloat16_rn(v);
    float lo = v - __bfloat162float(hi);
    g_xhi[i] = hi;
    g_xlo[i] = __float2bfloat16_rn(lo);
}

// W [K=FIN][N=HC] -> WT hi/lo [N][K]
__global__ __launch_bounds__(256) void w_splitT(
    const float* __restrict__ W, __nv_bfloat16* __restrict__ Thi,
    __nv_bfloat16* __restrict__ Tlo)
{
    __shared__ float tile[32][33];
    int tx = threadIdx.x & 31;
    int ty = threadIdx.x >> 5;
    int n0 = blockIdx.x * 32;
    int k0 = blockIdx.y * 32;
#pragma unroll
    for (int i = ty; i < 32; i += 8)
        tile[i][tx] = W[(size_t)(k0 + i) * HC + n0 + tx];
    __syncthreads();
#pragma unroll
    for (int i = ty; i < 32; i += 8) {
        float v = tile[tx][i];
        __nv_bfloat16 hi = __float2bfloat16_rn(v);
        float lo = v - __bfloat162float(hi);
        size_t o = (size_t)(n0 + i) * FIN + k0 + tx;
        Thi[o] = hi;
        Tlo[o] = __float2bfloat16_rn(lo);
    }
}

// ------------------------- HMMA bf16-split GEMM ------------------------------
#define KC       32
#define NCHUNK   (FIN / KC)        /* 32 */
#define STRIDE   20                /* uint32 per smem row (16 data + 4 pad) */
#define BUF_U32  (128 * STRIDE)
#define OFF_AHI  0
#define OFF_ALO  (1 * BUF_U32)
#define OFF_BHI  (2 * BUF_U32)
#define OFF_BLO  (3 * BUF_U32)
#define STAGE_U32 (4 * BUF_U32)
#define GEMM_SMEM (2 * STAGE_U32 * 4)   /* 81920 B */

__device__ __forceinline__ uint32_t smem_u32(const void* p) {
    uint32_t a;
    asm("{ .reg .u64 t; cvta.to.shared.u64 t, %1; cvt.u32.u64 %0, t; }"
        : "=r"(a) : "l"(p));
    return a;
}
__device__ __forceinline__ void cp16(uint32_t saddr, const void* g, int src_sz) {
    asm volatile("cp.async.cg.shared.global [%0], [%1], 16, %2;"
                 :: "r"(saddr), "l"(g), "r"(src_sz));
}
__device__ __forceinline__ void ldm_x4(uint32_t& r0, uint32_t& r1,
                                       uint32_t& r2, uint32_t& r3, uint32_t addr) {
    asm volatile("ldmatrix.sync.aligned.m8n8.x4.shared.b16 {%0,%1,%2,%3}, [%4];"
                 : "=r"(r0), "=r"(r1), "=r"(r2), "=r"(r3) : "r"(addr));
}
__device__ __forceinline__ void mma_bf16(float& c0, float& c1, float& c2, float& c3,
                                         uint32_t a0, uint32_t a1, uint32_t a2,
                                         uint32_t a3, uint32_t b0, uint32_t b1) {
    asm volatile(
        "mma.sync.aligned.m16n8k16.row.col.f32.bf16.bf16.f32 "
        "{%0,%1,%2,%3}, {%4,%5,%6,%7}, {%8,%9}, {%0,%1,%2,%3};"
        : "+f"(c0), "+f"(c1), "+f"(c2), "+f"(c3)
        : "r"(a0), "r"(a1), "r"(a2), "r"(a3), "r"(b0), "r"(b1));
}

__global__ __launch_bounds__(256) void gemm_mma(
    const __nv_bfloat16* __restrict__ Ahi, const __nv_bfloat16* __restrict__ Alo,
    const __nv_bfloat16* __restrict__ BThi, const __nv_bfloat16* __restrict__ BTlo,
    const float* __restrict__ bias, float* __restrict__ C, int M)
{
    extern __shared__ uint32_t smem[];
    const uint32_t sbase = smem_u32(smem);
    const int t = threadIdx.x;
    const int w = t >> 5;
    const int lane = t & 31;
    const int gid = lane >> 2;
    const int tg  = lane & 3;
    const int warpM = w & 1;
    const int warpN = w >> 1;
    const int rowBase = blockIdx.y * 128;
    const int colBase = blockIdx.x * 128;

    // ldmatrix per-lane address components
    const int a_row = (lane & 7) + ((lane >> 3) & 1) * 8;   // row within 16-row A tile
    const int a_kh  = (lane >> 4) & 1;                      // k half
    const int b_row = (lane & 7) + ((lane >> 4) & 1) * 8;   // row within 16-row B pair
    const int b_kh  = (lane >> 3) & 1;

    auto issue = [&](int c, int s) {
        const int k0 = c * KC;
        const uint32_t base = sbase + s * (STAGE_U32 * 4);
#pragma unroll
        for (int i = 0; i < 2; i++) {
            int idx = t + i * 256;
            int row = idx >> 2;
            int q   = idx & 3;
            uint32_t soff = (uint32_t)(row * STRIDE + q * 4) * 4;
            int ar = rowBase + row;
            int ok = (ar < M) ? 16 : 0;
            int arc = (ar < M) ? ar : 0;
            size_t ga = (size_t)arc * FIN + k0 + q * 8;
            cp16(base + OFF_AHI * 4 + soff, Ahi + ga, ok);
            cp16(base + OFF_ALO * 4 + soff, Alo + ga, ok);
            size_t gb = (size_t)(colBase + row) * FIN + k0 + q * 8;
            cp16(base + OFF_BHI * 4 + soff, BThi + gb, 16);
            cp16(base + OFF_BLO * 4 + soff, BTlo + gb, 16);
        }
        asm volatile("cp.async.commit_group;");
    };

    float acc[4][4][4];
#pragma unroll
    for (int mt = 0; mt < 4; mt++)
#pragma unroll
        for (int nt = 0; nt < 4; nt++)
#pragma unroll
            for (int r = 0; r < 4; r++) acc[mt][nt][r] = 0.f;

    issue(0, 0);

    for (int c = 0; c < NCHUNK; c++) {
        if (c + 1 < NCHUNK) {
            issue(c + 1, (c + 1) & 1);
            asm volatile("cp.async.wait_group 1;");
        } else {
            asm volatile("cp.async.wait_group 0;");
        }
        __syncthreads();

        const uint32_t sb = sbase + (c & 1) * (STAGE_U32 * 4);

#pragma unroll
        for (int ks = 0; ks < 2; ks++) {
            uint32_t ah[4][4], al[4][4];
#pragma unroll
            for (int mt = 0; mt < 4; mt++) {
                uint32_t ra = sb + OFF_AHI * 4 +
                    (uint32_t)(((warpM * 64 + mt * 16 + a_row) * STRIDE) +
                               ks * 8 + a_kh * 4) * 4;
                ldm_x4(ah[mt][0], ah[mt][1], ah[mt][2], ah[mt][3], ra);
                ldm_x4(al[mt][0], al[mt][1], al[mt][2], al[mt][3],
                       ra + (OFF_ALO - OFF_AHI) * 4);
            }
            uint32_t bh[4][2], bl[4][2];
#pragma unroll
            for (int ntp = 0; ntp < 2; ntp++) {
                uint32_t rb = sb + OFF_BHI * 4 +
                    (uint32_t)(((warpN * 32 + ntp * 16 + b_row) * STRIDE) +
                               ks * 8 + b_kh * 4) * 4;
                ldm_x4(bh[2 * ntp][0], bh[2 * ntp][1],
                       bh[2 * ntp + 1][0], bh[2 * ntp + 1][1], rb);
                ldm_x4(bl[2 * ntp][0], bl[2 * ntp][1],
                       bl[2 * ntp + 1][0], bl[2 * ntp + 1][1],
                       rb + (OFF_BLO - OFF_BHI) * 4);
            }
#pragma unroll
            for (int nt = 0; nt < 4; nt++) {
#pragma unroll
                for (int mt = 0; mt < 4; mt++) {
                    float* cc = acc[mt][nt];
                    mma_bf16(cc[0], cc[1], cc[2], cc[3],
                             ah[mt][0], ah[mt][1], ah[mt][2], ah[mt][3],
                             bh[nt][0], bh[nt][1]);
                    mma_bf16(cc[0], cc[1], cc[2], cc[3],
                             ah[mt][0], ah[mt][1], ah[mt][2], ah[mt][3],
                             bl[nt][0], bl[nt][1]);
                    mma_bf16(cc[0], cc[1], cc[2], cc[3],
                             al[mt][0], al[mt][1], al[mt][2], al[mt][3],
                             bh[nt][0], bh[nt][1]);
                }
            }
        }
        __syncthreads();
    }

#pragma unroll
    for (int mt = 0; mt < 4; mt++) {
        int r0 = rowBase + warpM * 64 + mt * 16 + gid;
        int r1 = r0 + 8;
#pragma unroll
        for (int nt = 0; nt < 4; nt++) {
            int cb = colBase + warpN * 32 + nt * 8 + tg * 2;
            float b0 = bias[cb], b1 = bias[cb + 1];
            if (r0 < M) {
                float2 o = make_float2(acc[mt][nt][0] + b0, acc[mt][nt][1] + b1);
                *(float2*)(C + (size_t)r0 * HC + cb) = o;
            }
            if (r1 < M) {
                float2 o = make_float2(acc[mt][nt][2] + b0, acc[mt][nt][3] + b1);
                *(float2*)(C + (size_t)r1 * HC + cb) = o;
            }
        }
    }
}

// ------------------------- SIMT SGEMM for fc readout ------------------------
__global__ __launch_bounds__(256) void sgemm_bias(
    const float* __restrict__ B, const float* __restrict__ bias,
    float* __restrict__ C, int M, int Nn, int K)
{
    const float* A = g_hmean;
    __shared__ float As[8][128];
    __shared__ float Bs[8][128];
    const int tid = threadIdx.x;
    const int tx  = tid & 15;
    const int ty  = tid >> 4;
    const int rowBase = blockIdx.y * 128;
    const int colBase = blockIdx.x * 128;
    const int aRow = tid >> 1;
    const int aCol = (tid & 1) * 4;
    const int bRow = tid >> 5;
    const int bCol = (tid & 31) * 4;

    float acc[8][8];
#pragma unroll
    for (int i = 0; i < 8; i++)
#pragma unroll
        for (int j = 0; j < 8; j++) acc[i][j] = 0.f;

    for (int k0 = 0; k0 < K; k0 += 8) {
        float4 av = make_float4(0.f, 0.f, 0.f, 0.f);
        int ar = rowBase + aRow;
        if (ar < M) av = *(const float4*)(A + (size_t)ar * K + k0 + aCol);
        As[aCol + 0][aRow] = av.x;
        As[aCol + 1][aRow] = av.y;
        As[aCol + 2][aRow] = av.z;
        As[aCol + 3][aRow] = av.w;
        float4 bv = make_float4(0.f, 0.f, 0.f, 0.f);
        int bc = colBase + bCol;
        if (bc < Nn)
            bv = *(const float4*)(B + (size_t)(k0 + bRow) * Nn + bc);
        *(float4*)&Bs[bRow][bCol] = bv;
        __syncthreads();
#pragma unroll
        for (int kk = 0; kk < 8; kk++) {
            float aR[8], bR[8];
#pragma unroll
            for (int i = 0; i < 8; i++) aR[i] = As[kk][ty * 8 + i];
#pragma unroll
            for (int j = 0; j < 8; j++) bR[j] = Bs[kk][tx * 8 + j];
#pragma unroll
            for (int i = 0; i < 8; i++)
#pragma unroll
                for (int j = 0; j < 8; j++) acc[i][j] += aR[i] * bR[j];
        }
        __syncthreads();
    }
#pragma unroll
    for (int i = 0; i < 8; i++) {
        int r = rowBase + ty * 8 + i;
        if (r >= M) continue;
#pragma unroll
        for (int j = 0; j < 8; j += 4) {
            int c = colBase + tx * 8 + j;
            if (c < Nn) {
                float4 o;
                o.x = acc[i][j + 0] + bias[c + 0];
                o.y = acc[i][j + 1] + bias[c + 1];
                o.z = acc[i][j + 2] + bias[c + 2];
                o.w = acc[i][j + 3] + bias[c + 3];
                *(float4*)(C + (size_t)r * Nn + c) = o;
            }
        }
    }
}

// ------------------------- CSR build ---------------------------------------
__global__ void k_zero_counts()
{
    int i = blockIdx.x * blockDim.x + threadIdx.x;
    if (i < NNODES) g_count[i] = 0;
}
__global__ void k_count(const int* __restrict__ ei)
{
    int e = blockIdx.x * blockDim.x + threadIdx.x;
    if (e >= ET) return;
    int dst = (e < NEDGES) ? ei[2 * e + 1] : (e - NEDGES);
    atomicAdd(&g_count[dst], 1);
}
__global__ __launch_bounds__(1024) void k_scan()
{
    __shared__ int sh[1024];
    __shared__ int carry;
    int tid = threadIdx.x;
    if (tid == 0) carry = 0;
    __syncthreads();
    for (int base = 0; base < NNODES; base += 1024) {
        int i = base + tid;
        int v = (i < NNODES) ? g_count[i] : 0;
        sh[tid] = v;
        __syncthreads();
        for (int off = 1; off < 1024; off <<= 1) {
            int t = (tid >= off) ? sh[tid - off] : 0;
            __syncthreads();
            sh[tid] += t;
            __syncthreads();
        }
        int excl = carry + sh[tid] - v;
        if (i < NNODES) { g_rowstart[i] = excl; g_cursor[i] = excl; }
        __syncthreads();
        if (tid == 1023) carry += sh[1023];
        __syncthreads();
    }
    if (tid == 0) g_rowstart[NNODES] = carry;
}
// store SRC node id directly (edge identity no longer needed downstream)
__global__ void k_scatter(const int* __restrict__ ei)
{
    int e = blockIdx.x * blockDim.x + threadIdx.x;
    if (e >= ET) return;
    int src, dst;
    if (e < NEDGES) { src = ei[2 * e]; dst = ei[2 * e + 1]; }
    else            { src = dst = e - NEDGES; }
    int pos = atomicAdd(&g_cursor[dst], 1);
    g_csr[pos] = src;
}

// ------------------------- fused scores + softmax + aggregate ---------------
// One block (128 threads) per destination node. Online softmax over incoming
// edges; reads xl[src] ONCE per edge (score + aggregation in the same pass).
__global__ __launch_bounds__(128) void node_fused(
    const float* __restrict__ att, const float* __restrict__ bias)
{
    __shared__ float4 satt[HC / 4];      // 12 KB
    __shared__ float  red[4][NH];

    const int node = blockIdx.x;
    const int t = threadIdx.x;
    const int w = t >> 5;
    const int lane = t & 31;

    for (int i = t; i < HC / 4; i += 128)
        satt[i] = ((const float4*)att)[i];

    const int beg = g_rowstart[node];
    const int end = g_rowstart[node + 1];

    // xr[dst] resident in registers
    float4 xr[NH][2];
    {
        const float4* xrp = (const float4*)(g_xr + (size_t)node * HC);
#pragma unroll
        for (int h = 0; h < NH; h++)
#pragma unroll
            for (int q = 0; q < 2; q++)
                xr[h][q] = xrp[h * 256 + t + 128 * q];
    }
    __syncthreads();

    float m[NH], d[NH];
    float4 acc[NH][2];
#pragma unroll
    for (int h = 0; h < NH; h++) {
        m[h] = -3.0e38f;
        d[h] = 0.f;
#pragma unroll
        for (int q = 0; q < 2; q++) acc[h][q] = make_float4(0.f, 0.f, 0.f, 0.f);
    }

    for (int p = beg; p < end; p++) {
        int src = g_csr[p];
        const float4* xlp = (const float4*)(g_xl + (size_t)src * HC);
        float4 xl[NH][2];
        float part[NH];
#pragma unroll
        for (int h = 0; h < NH; h++) {
            part[h] = 0.f;
#pragma unroll
            for (int q = 0; q < 2; q++) {
                float4 v = xlp[h * 256 + t + 128 * q];
                xl[h][q] = v;
                float4 r = xr[h][q];
                float4 a = satt[h * 256 + t + 128 * q];
                float sx = v.x + r.x; sx = sx > 0.f ? sx : 0.2f * sx;
                float sy = v.y + r.y; sy = sy > 0.f ? sy : 0.2f * sy;
                float sz = v.z + r.z; sz = sz > 0.f ? sz : 0.2f * sz;
                float sw = v.w + r.w; sw = sw > 0.f ? sw : 0.2f * sw;
                part[h] += sx * a.x + sy * a.y + sz * a.z + sw * a.w;
            }
        }
#pragma unroll
        for (int off = 16; off; off >>= 1)
#pragma unroll
            for (int h = 0; h < NH; h++)
                part[h] += __shfl_xor_sync(0xFFFFFFFFu, part[h], off);
        if (lane == 0)
#pragma unroll
            for (int h = 0; h < NH; h++) red[w][h] = part[h];
        __syncthreads();

        float s[NH];
#pragma unroll
        for (int h = 0; h < NH; h++)
            s[h] = red[0][h] + red[1][h] + red[2][h] + red[3][h];
        __syncthreads();

#pragma unroll
        for (int h = 0; h < NH; h++) {
            float e;
            if (s[h] > m[h]) {
                float sc = __expf(m[h] - s[h]);   // 0 on first edge (m=-inf)
                d[h] *= sc;
#pragma unroll
                for (int q = 0; q < 2; q++) {
                    acc[h][q].x *= sc; acc[h][q].y *= sc;
                    acc[h][q].z *= sc; acc[h][q].w *= sc;
                }
                m[h] = s[h];
                e = 1.f;
            } else {
                e = __expf(s[h] - m[h]);
            }
            d[h] += e;
#pragma unroll
            for (int q = 0; q < 2; q++) {
                acc[h][q].x += e * xl[h][q].x;
                acc[h][q].y += e * xl[h][q].y;
                acc[h][q].z += e * xl[h][q].z;
                acc[h][q].w += e * xl[h][q].w;
            }
        }
    }

    float invd[NH];
#pragma unroll
    for (int h = 0; h < NH; h++) invd[h] = 1.f / (d[h] + 1e-16f);

    const float inv3 = 1.0f / 3.0f;
#pragma unroll
    for (int q = 0; q < 2; q++) {
        int f = t + 128 * q;
        float4 o;
        o.x = (acc[0][q].x * invd[0] + acc[1][q].x * invd[1] + acc[2][q].x * invd[2]) * inv3 + bias[4 * f + 0];
        o.y = (acc[0][q].y * invd[0] + acc[1][q].y * invd[1] + acc[2][q].y * invd[2]) * inv3 + bias[4 * f + 1];
        o.z = (acc[0][q].z * invd[0] + acc[1][q].z * invd[1] + acc[2][q].z * invd[2]) * inv3 + bias[4 * f + 2];
        o.w = (acc[0][q].w * invd[0] + acc[1][q].w * invd[1] + acc[2][q].w * invd[2]) * inv3 + bias[4 * f + 3];
        *(float4*)(g_hmean + (size_t)node * CH + 4 * f) = o;
    }
}

// ------------------------- pass-through copy --------------------------------
__global__ void k_copy4(const float4* __restrict__ src, float4* __restrict__ dst,
                        int n4)
{
    int i = blockIdx.x * blockDim.x + threadIdx.x;
    if (i < n4) dst[i] = src[i];
}

// ------------------------- launch ------------------------------------------
extern "C" void kernel_launch(void* const* d_in, const int* in_sizes, int n_in,
                              void* d_out, int out_size)
{
    const float* x    = (const float*)d_in[0];
    const int*   ei   = (const int*)d_in[1];
    const float* Wl   = (const float*)d_in[2];
    const float* bl   = (const float*)d_in[3];
    const float* Wr   = (const float*)d_in[4];
    const float* br   = (const float*)d_in[5];
    const float* att  = (const float*)d_in[6];
    const float* bias = (const float*)d_in[7];
    const float* Wfc  = (const float*)d_in[8];
    const float* bfc  = (const float*)d_in[9];
    const float* exps   = (const float*)d_in[10];
    const float* exps_c = (const float*)d_in[11];
    float* out = (float*)d_out;

    cudaFuncSetAttribute(gemm_mma, cudaFuncAttributeMaxDynamicSharedMemorySize,
                         GEMM_SMEM);

    // device addresses (NOT host shadow symbols — GB300 ATS trap)
    float *pxl, *pxr;
    __nv_bfloat16 *pxhi, *pxlo, *plThi, *plTlo, *prThi, *prTlo;
    cudaGetSymbolAddress((void**)&pxl,   g_xl);
    cudaGetSymbolAddress((void**)&pxr,   g_xr);
    cudaGetSymbolAddress((void**)&pxhi,  g_xhi);
    cudaGetSymbolAddress((void**)&pxlo,  g_xlo);
    cudaGetSymbolAddress((void**)&plThi, g_wlThi);
    cudaGetSymbolAddress((void**)&plTlo, g_wlTlo);
    cudaGetSymbolAddress((void**)&prThi, g_wrThi);
    cudaGetSymbolAddress((void**)&prTlo, g_wrTlo);

    // bf16 hi/lo splits of x and W^T
    x_split<<<(NNODES * FIN + 255) / 256, 256>>>(x);
    {
        dim3 grid(HC / 32, FIN / 32);
        w_splitT<<<grid, 256>>>(Wl, plThi, plTlo);
        w_splitT<<<grid, 256>>>(Wr, prThi, prTlo);
    }

    // projections on tensor cores
    {
        dim3 grid(HC / 128, (NNODES + 127) / 128);
        gemm_mma<<<grid, 256, GEMM_SMEM>>>(pxhi, pxlo, plThi, plTlo,
                                           bl, pxl, NNODES);
        gemm_mma<<<grid, 256, GEMM_SMEM>>>(pxhi, pxlo, prThi, prTlo,
                                           br, pxr, NNODES);
    }

    // CSR by destination (src stored per slot)
    k_zero_counts<<<(NNODES + 255) / 256, 256>>>();
    k_count<<<(ET + 255) / 256, 256>>>(ei);
    k_scan<<<1, 1024>>>();
    k_scatter<<<(ET + 255) / 256, 256>>>(ei);

    // fused scores + online softmax + aggregation + head mean + bias
    node_fused<<<NNODES, 128>>>(att, bias);

    // fc readout
    {
        dim3 grid((NCLS + 127) / 128, (NNODES + 127) / 128);
        sgemm_bias<<<grid, 256>>>(Wfc, bfc, out, NNODES, NCLS, FIN);
    }

    // pass-through outputs
    size_t hElems = (size_t)NNODES * NCLS;
    int n4a = in_sizes[10] / 4;
    int n4b = in_sizes[11] / 4;
    k_copy4<<<(n4a + 255) / 256, 256>>>((const float4*)exps,
                                        (float4*)(out + hElems), n4a);
    k_copy4<<<(n4b + 255) / 256, 256>>>((const float4*)exps_c,
                                        (float4*)(out + hElems + in_sizes[10]), n4b);
}

// round 9
// speedup vs baseline: 2.5035x; 1.1257x over previous
#include <cuda_runtime.h>
#include <cuda_bf16.h>
#include <math.h>
#include <stdint.h>

#define NNODES 10000
#define NEDGES 100000
#define NH     3
#define CH     1024
#define HC     3072          /* NH*CH */
#define ET     110000        /* NEDGES + NNODES self loops */
#define NCLS   460
#define FIN    1024

// ------------------------- scratch (device globals, no allocs) -------------
__device__ float g_xl[(size_t)NNODES * HC];
__device__ float g_xr[(size_t)NNODES * HC];
__device__ float g_hmean[(size_t)NNODES * CH];
__device__ int   g_count[NNODES];
__device__ int   g_rowstart[NNODES + 1];
__device__ int   g_cursor[NNODES];
__device__ int   g_csr[ET];                      // stores SRC node per slot
// bf16 hi/lo splits
__device__ __nv_bfloat16 g_xhi[(size_t)NNODES * FIN];
__device__ __nv_bfloat16 g_xlo[(size_t)NNODES * FIN];
__device__ __nv_bfloat16 g_wlThi[(size_t)HC * FIN];   // Wl^T [N=HC][K=FIN]
__device__ __nv_bfloat16 g_wlTlo[(size_t)HC * FIN];
__device__ __nv_bfloat16 g_wrThi[(size_t)HC * FIN];
__device__ __nv_bfloat16 g_wrTlo[(size_t)HC * FIN];
__device__ __nv_bfloat16 g_hmhi[(size_t)NNODES * CH];
__device__ __nv_bfloat16 g_hmlo[(size_t)NNODES * CH];
__device__ __nv_bfloat16 g_wfcThi[(size_t)512 * CH];  // Wfc^T padded rows
__device__ __nv_bfloat16 g_wfcTlo[(size_t)512 * CH];

// ------------------------- split/transpose prep -----------------------------
__global__ void x_split(const float* __restrict__ x)
{
    int i = blockIdx.x * blockDim.x + threadIdx.x;
    if (i >= NNODES * FIN) return;
    float v = x[i];
    __nv_bfloat16 hi = __float2bfloat16_rn(v);
    float lo = v - __bfloat162float(hi);
    g_xhi[i] = hi;
    g_xlo[i] = __float2bfloat16_rn(lo);
}

__global__ void hm_split()
{
    int i = blockIdx.x * blockDim.x + threadIdx.x;
    if (i >= NNODES * CH) return;
    float v = g_hmean[i];
    __nv_bfloat16 hi = __float2bfloat16_rn(v);
    float lo = v - __bfloat162float(hi);
    g_hmhi[i] = hi;
    g_hmlo[i] = __float2bfloat16_rn(lo);
}

// W [K][Ntot] -> T hi/lo [Ntot][K]  (generalized, clamped)
__global__ __launch_bounds__(256) void w_splitT_g(
    const float* __restrict__ W, __nv_bfloat16* __restrict__ Thi,
    __nv_bfloat16* __restrict__ Tlo, int Ntot, int K)
{
    __shared__ float tile[32][33];
    int tx = threadIdx.x & 31;
    int ty = threadIdx.x >> 5;
    int n0 = blockIdx.x * 32;
    int k0 = blockIdx.y * 32;
#pragma unroll
    for (int i = ty; i < 32; i += 8) {
        float v = 0.f;
        if (n0 + tx < Ntot) v = W[(size_t)(k0 + i) * Ntot + n0 + tx];
        tile[i][tx] = v;
    }
    __syncthreads();
#pragma unroll
    for (int i = ty; i < 32; i += 8) {
        if (n0 + i < Ntot) {
            float v = tile[tx][i];
            __nv_bfloat16 hi = __float2bfloat16_rn(v);
            float lo = v - __bfloat162float(hi);
            size_t o = (size_t)(n0 + i) * K + k0 + tx;
            Thi[o] = hi;
            Tlo[o] = __float2bfloat16_rn(lo);
        }
    }
}

// ------------------------- HMMA bf16-split GEMM ------------------------------
#define KC       32
#define NCHUNK   (FIN / KC)        /* 32 */
#define STRIDE   20                /* uint32 per smem row (16 data + 4 pad) */
#define BUF_U32  (128 * STRIDE)
#define OFF_AHI  0
#define OFF_ALO  (1 * BUF_U32)
#define OFF_BHI  (2 * BUF_U32)
#define OFF_BLO  (3 * BUF_U32)
#define STAGE_U32 (4 * BUF_U32)
#define GEMM_SMEM (2 * STAGE_U32 * 4)   /* 81920 B */

__device__ __forceinline__ uint32_t smem_u32(const void* p) {
    uint32_t a;
    asm("{ .reg .u64 t; cvta.to.shared.u64 t, %1; cvt.u32.u64 %0, t; }"
        : "=r"(a) : "l"(p));
    return a;
}
__device__ __forceinline__ void cp16(uint32_t saddr, const void* g, int src_sz) {
    asm volatile("cp.async.cg.shared.global [%0], [%1], 16, %2;"
                 :: "r"(saddr), "l"(g), "r"(src_sz));
}
__device__ __forceinline__ void ldm_x4(uint32_t& r0, uint32_t& r1,
                                       uint32_t& r2, uint32_t& r3, uint32_t addr) {
    asm volatile("ldmatrix.sync.aligned.m8n8.x4.shared.b16 {%0,%1,%2,%3}, [%4];"
                 : "=r"(r0), "=r"(r1), "=r"(r2), "=r"(r3) : "r"(addr));
}
__device__ __forceinline__ void mma_bf16(float& c0, float& c1, float& c2, float& c3,
                                         uint32_t a0, uint32_t a1, uint32_t a2,
                                         uint32_t a3, uint32_t b0, uint32_t b1) {
    asm volatile(
        "mma.sync.aligned.m16n8k16.row.col.f32.bf16.bf16.f32 "
        "{%0,%1,%2,%3}, {%4,%5,%6,%7}, {%8,%9}, {%0,%1,%2,%3};"
        : "+f"(c0), "+f"(c1), "+f"(c2), "+f"(c3)
        : "r"(a0), "r"(a1), "r"(a2), "r"(a3), "r"(b0), "r"(b1));
}

// C[M x Nn] (row stride ldC) = A[M x FIN] @ BT[Nn x FIN]^T + bias[Nn]
__global__ __launch_bounds__(256) void gemm_mma(
    const __nv_bfloat16* __restrict__ Ahi, const __nv_bfloat16* __restrict__ Alo,
    const __nv_bfloat16* __restrict__ BThi, const __nv_bfloat16* __restrict__ BTlo,
    const float* __restrict__ bias, float* __restrict__ C,
    int M, int Nn, int ldC)
{
    extern __shared__ uint32_t smem[];
    const uint32_t sbase = smem_u32(smem);
    const int t = threadIdx.x;
    const int w = t >> 5;
    const int lane = t & 31;
    const int gid = lane >> 2;
    const int tg  = lane & 3;
    const int warpM = w & 1;
    const int warpN = w >> 1;
    const int rowBase = blockIdx.y * 128;
    const int colBase = blockIdx.x * 128;

    const int a_row = (lane & 7) + ((lane >> 3) & 1) * 8;
    const int a_kh  = (lane >> 4) & 1;
    const int b_row = (lane & 7) + ((lane >> 4) & 1) * 8;
    const int b_kh  = (lane >> 3) & 1;

    auto issue = [&](int c, int s) {
        const int k0 = c * KC;
        const uint32_t base = sbase + s * (STAGE_U32 * 4);
#pragma unroll
        for (int i = 0; i < 2; i++) {
            int idx = t + i * 256;
            int row = idx >> 2;
            int q   = idx & 3;
            uint32_t soff = (uint32_t)(row * STRIDE + q * 4) * 4;
            int ar = rowBase + row;
            int ok = (ar < M) ? 16 : 0;
            int arc = (ar < M) ? ar : 0;
            size_t ga = (size_t)arc * FIN + k0 + q * 8;
            cp16(base + OFF_AHI * 4 + soff, Ahi + ga, ok);
            cp16(base + OFF_ALO * 4 + soff, Alo + ga, ok);
            int br = colBase + row;
            int okb = (br < Nn) ? 16 : 0;
            int brc = (br < Nn) ? br : 0;
            size_t gb = (size_t)brc * FIN + k0 + q * 8;
            cp16(base + OFF_BHI * 4 + soff, BThi + gb, okb);
            cp16(base + OFF_BLO * 4 + soff, BTlo + gb, okb);
        }
        asm volatile("cp.async.commit_group;");
    };

    float acc[4][4][4];
#pragma unroll
    for (int mt = 0; mt < 4; mt++)
#pragma unroll
        for (int nt = 0; nt < 4; nt++)
#pragma unroll
            for (int r = 0; r < 4; r++) acc[mt][nt][r] = 0.f;

    issue(0, 0);

    for (int c = 0; c < NCHUNK; c++) {
        if (c + 1 < NCHUNK) {
            issue(c + 1, (c + 1) & 1);
            asm volatile("cp.async.wait_group 1;");
        } else {
            asm volatile("cp.async.wait_group 0;");
        }
        __syncthreads();

        const uint32_t sb = sbase + (c & 1) * (STAGE_U32 * 4);

#pragma unroll
        for (int ks = 0; ks < 2; ks++) {
            uint32_t ah[4][4], al[4][4];
#pragma unroll
            for (int mt = 0; mt < 4; mt++) {
                uint32_t ra = sb + OFF_AHI * 4 +
                    (uint32_t)(((warpM * 64 + mt * 16 + a_row) * STRIDE) +
                               ks * 8 + a_kh * 4) * 4;
                ldm_x4(ah[mt][0], ah[mt][1], ah[mt][2], ah[mt][3], ra);
                ldm_x4(al[mt][0], al[mt][1], al[mt][2], al[mt][3],
                       ra + (OFF_ALO - OFF_AHI) * 4);
            }
            uint32_t bh[4][2], bl[4][2];
#pragma unroll
            for (int ntp = 0; ntp < 2; ntp++) {
                uint32_t rb = sb + OFF_BHI * 4 +
                    (uint32_t)(((warpN * 32 + ntp * 16 + b_row) * STRIDE) +
                               ks * 8 + b_kh * 4) * 4;
                ldm_x4(bh[2 * ntp][0], bh[2 * ntp][1],
                       bh[2 * ntp + 1][0], bh[2 * ntp + 1][1], rb);
                ldm_x4(bl[2 * ntp][0], bl[2 * ntp][1],
                       bl[2 * ntp + 1][0], bl[2 * ntp + 1][1],
                       rb + (OFF_BLO - OFF_BHI) * 4);
            }
#pragma unroll
            for (int nt = 0; nt < 4; nt++) {
#pragma unroll
                for (int mt = 0; mt < 4; mt++) {
                    float* cc = acc[mt][nt];
                    mma_bf16(cc[0], cc[1], cc[2], cc[3],
                             ah[mt][0], ah[mt][1], ah[mt][2], ah[mt][3],
                             bh[nt][0], bh[nt][1]);
                    mma_bf16(cc[0], cc[1], cc[2], cc[3],
                             ah[mt][0], ah[mt][1], ah[mt][2], ah[mt][3],
                             bl[nt][0], bl[nt][1]);
                    mma_bf16(cc[0], cc[1], cc[2], cc[3],
                             al[mt][0], al[mt][1], al[mt][2], al[mt][3],
                             bh[nt][0], bh[nt][1]);
                }
            }
        }
        __syncthreads();
    }

#pragma unroll
    for (int mt = 0; mt < 4; mt++) {
        int r0 = rowBase + warpM * 64 + mt * 16 + gid;
        int r1 = r0 + 8;
#pragma unroll
        for (int nt = 0; nt < 4; nt++) {
            int cb = colBase + warpN * 32 + nt * 8 + tg * 2;
            if (cb >= Nn) continue;
            float b0 = bias[cb], b1 = bias[cb + 1];
            if (r0 < M) {
                float2 o = make_float2(acc[mt][nt][0] + b0, acc[mt][nt][1] + b1);
                *(float2*)(C + (size_t)r0 * ldC + cb) = o;
            }
            if (r1 < M) {
                float2 o = make_float2(acc[mt][nt][2] + b0, acc[mt][nt][3] + b1);
                *(float2*)(C + (size_t)r1 * ldC + cb) = o;
            }
        }
    }
}

// ------------------------- CSR build ---------------------------------------
__global__ void k_zero_counts()
{
    int i = blockIdx.x * blockDim.x + threadIdx.x;
    if (i < NNODES) g_count[i] = 0;
}
__global__ void k_count(const int* __restrict__ ei)
{
    int e = blockIdx.x * blockDim.x + threadIdx.x;
    if (e >= ET) return;
    int dst = (e < NEDGES) ? ei[2 * e + 1] : (e - NEDGES);
    atomicAdd(&g_count[dst], 1);
}
__global__ __launch_bounds__(1024) void k_scan()
{
    __shared__ int sh[1024];
    __shared__ int carry;
    int tid = threadIdx.x;
    if (tid == 0) carry = 0;
    __syncthreads();
    for (int base = 0; base < NNODES; base += 1024) {
        int i = base + tid;
        int v = (i < NNODES) ? g_count[i] : 0;
        sh[tid] = v;
        __syncthreads();
        for (int off = 1; off < 1024; off <<= 1) {
            int t = (tid >= off) ? sh[tid - off] : 0;
            __syncthreads();
            sh[tid] += t;
            __syncthreads();
        }
        int excl = carry + sh[tid] - v;
        if (i < NNODES) { g_rowstart[i] = excl; g_cursor[i] = excl; }
        __syncthreads();
        if (tid == 1023) carry += sh[1023];
        __syncthreads();
    }
    if (tid == 0) g_rowstart[NNODES] = carry;
}
__global__ void k_scatter(const int* __restrict__ ei)
{
    int e = blockIdx.x * blockDim.x + threadIdx.x;
    if (e >= ET) return;
    int src, dst;
    if (e < NEDGES) { src = ei[2 * e]; dst = ei[2 * e + 1]; }
    else            { src = dst = e - NEDGES; }
    int pos = atomicAdd(&g_cursor[dst], 1);
    g_csr[pos] = src;
}

// ------------------------- fused scores + softmax + aggregate ---------------
__global__ __launch_bounds__(128) void node_fused(
    const float* __restrict__ att, const float* __restrict__ bias)
{
    __shared__ float4 satt[HC / 4];
    __shared__ float  red[4][NH];

    const int node = blockIdx.x;
    const int t = threadIdx.x;
    const int w = t >> 5;
    const int lane = t & 31;

    for (int i = t; i < HC / 4; i += 128)
        satt[i] = ((const float4*)att)[i];

    const int beg = g_rowstart[node];
    const int end = g_rowstart[node + 1];

    float4 xr[NH][2];
    {
        const float4* xrp = (const float4*)(g_xr + (size_t)node * HC);
#pragma unroll
        for (int h = 0; h < NH; h++)
#pragma unroll
            for (int q = 0; q < 2; q++)
                xr[h][q] = xrp[h * 256 + t + 128 * q];
    }
    __syncthreads();

    float m[NH], d[NH];
    float4 acc[NH][2];
#pragma unroll
    for (int h = 0; h < NH; h++) {
        m[h] = -3.0e38f;
        d[h] = 0.f;
#pragma unroll
        for (int q = 0; q < 2; q++) acc[h][q] = make_float4(0.f, 0.f, 0.f, 0.f);
    }

    for (int p = beg; p < end; p++) {
        int src = g_csr[p];
        const float4* xlp = (const float4*)(g_xl + (size_t)src * HC);
        float4 xl[NH][2];
        float part[NH];
#pragma unroll
        for (int h = 0; h < NH; h++) {
            part[h] = 0.f;
#pragma unroll
            for (int q = 0; q < 2; q++) {
                float4 v = xlp[h * 256 + t + 128 * q];
                xl[h][q] = v;
                float4 r = xr[h][q];
                float4 a = satt[h * 256 + t + 128 * q];
                float sx = v.x + r.x; sx = sx > 0.f ? sx : 0.2f * sx;
                float sy = v.y + r.y; sy = sy > 0.f ? sy : 0.2f * sy;
                float sz = v.z + r.z; sz = sz > 0.f ? sz : 0.2f * sz;
                float sw = v.w + r.w; sw = sw > 0.f ? sw : 0.2f * sw;
                part[h] += sx * a.x + sy * a.y + sz * a.z + sw * a.w;
            }
        }
#pragma unroll
        for (int off = 16; off; off >>= 1)
#pragma unroll
            for (int h = 0; h < NH; h++)
                part[h] += __shfl_xor_sync(0xFFFFFFFFu, part[h], off);
        if (lane == 0)
#pragma unroll
            for (int h = 0; h < NH; h++) red[w][h] = part[h];
        __syncthreads();

        float s[NH];
#pragma unroll
        for (int h = 0; h < NH; h++)
            s[h] = red[0][h] + red[1][h] + red[2][h] + red[3][h];
        __syncthreads();

#pragma unroll
        for (int h = 0; h < NH; h++) {
            float e;
            if (s[h] > m[h]) {
                float sc = __expf(m[h] - s[h]);
                d[h] *= sc;
#pragma unroll
                for (int q = 0; q < 2; q++) {
                    acc[h][q].x *= sc; acc[h][q].y *= sc;
                    acc[h][q].z *= sc; acc[h][q].w *= sc;
                }
                m[h] = s[h];
                e = 1.f;
            } else {
                e = __expf(s[h] - m[h]);
            }
            d[h] += e;
#pragma unroll
            for (int q = 0; q < 2; q++) {
                acc[h][q].x += e * xl[h][q].x;
                acc[h][q].y += e * xl[h][q].y;
                acc[h][q].z += e * xl[h][q].z;
                acc[h][q].w += e * xl[h][q].w;
            }
        }
    }

    float invd[NH];
#pragma unroll
    for (int h = 0; h < NH; h++) invd[h] = 1.f / (d[h] + 1e-16f);

    const float inv3 = 1.0f / 3.0f;
#pragma unroll
    for (int q = 0; q < 2; q++) {
        int f = t + 128 * q;
        float4 o;
        o.x = (acc[0][q].x * invd[0] + acc[1][q].x * invd[1] + acc[2][q].x * invd[2]) * inv3 + bias[4 * f + 0];
        o.y = (acc[0][q].y * invd[0] + acc[1][q].y * invd[1] + acc[2][q].y * invd[2]) * inv3 + bias[4 * f + 1];
        o.z = (acc[0][q].z * invd[0] + acc[1][q].z * invd[1] + acc[2][q].z * invd[2]) * inv3 + bias[4 * f + 2];
        o.w = (acc[0][q].w * invd[0] + acc[1][q].w * invd[1] + acc[2][q].w * invd[2]) * inv3 + bias[4 * f + 3];
        *(float4*)(g_hmean + (size_t)node * CH + 4 * f) = o;
    }
}

// ------------------------- pass-through copy --------------------------------
__global__ void k_copy4(const float4* __restrict__ src, float4* __restrict__ dst,
                        int n4)
{
    int i = blockIdx.x * blockDim.x + threadIdx.x;
    if (i < n4) dst[i] = src[i];
}

// ------------------------- launch ------------------------------------------
extern "C" void kernel_launch(void* const* d_in, const int* in_sizes, int n_in,
                              void* d_out, int out_size)
{
    const float* x    = (const float*)d_in[0];
    const int*   ei   = (const int*)d_in[1];
    const float* Wl   = (const float*)d_in[2];
    const float* bl   = (const float*)d_in[3];
    const float* Wr   = (const float*)d_in[4];
    const float* br   = (const float*)d_in[5];
    const float* att  = (const float*)d_in[6];
    const float* bias = (const float*)d_in[7];
    const float* Wfc  = (const float*)d_in[8];
    const float* bfc  = (const float*)d_in[9];
    const float* exps   = (const float*)d_in[10];
    const float* exps_c = (const float*)d_in[11];
    float* out = (float*)d_out;

    cudaFuncSetAttribute(gemm_mma, cudaFuncAttributeMaxDynamicSharedMemorySize,
                         GEMM_SMEM);

    // device addresses (NOT host shadow symbols — GB300 ATS trap)
    float *pxl, *pxr;
    __nv_bfloat16 *pxhi, *pxlo, *plThi, *plTlo, *prThi, *prTlo;
    __nv_bfloat16 *phmhi, *phmlo, *pfcThi, *pfcTlo;
    cudaGetSymbolAddress((void**)&pxl,    g_xl);
    cudaGetSymbolAddress((void**)&pxr,    g_xr);
    cudaGetSymbolAddress((void**)&pxhi,   g_xhi);
    cudaGetSymbolAddress((void**)&pxlo,   g_xlo);
    cudaGetSymbolAddress((void**)&plThi,  g_wlThi);
    cudaGetSymbolAddress((void**)&plTlo,  g_wlTlo);
    cudaGetSymbolAddress((void**)&prThi,  g_wrThi);
    cudaGetSymbolAddress((void**)&prTlo,  g_wrTlo);
    cudaGetSymbolAddress((void**)&phmhi,  g_hmhi);
    cudaGetSymbolAddress((void**)&phmlo,  g_hmlo);
    cudaGetSymbolAddress((void**)&pfcThi, g_wfcThi);
    cudaGetSymbolAddress((void**)&pfcTlo, g_wfcTlo);

    // bf16 hi/lo splits of x and W^T
    x_split<<<(NNODES * FIN + 255) / 256, 256>>>(x);
    {
        dim3 grid(HC / 32, FIN / 32);
        w_splitT_g<<<grid, 256>>>(Wl, plThi, plTlo, HC, FIN);
        w_splitT_g<<<grid, 256>>>(Wr, prThi, prTlo, HC, FIN);
    }
    {
        dim3 grid((NCLS + 31) / 32, CH / 32);
        w_splitT_g<<<grid, 256>>>(Wfc, pfcThi, pfcTlo, NCLS, CH);
    }

    // projections on tensor cores
    {
        dim3 grid(HC / 128, (NNODES + 127) / 128);
        gemm_mma<<<grid, 256, GEMM_SMEM>>>(pxhi, pxlo, plThi, plTlo,
                                           bl, pxl, NNODES, HC, HC);
        gemm_mma<<<grid, 256, GEMM_SMEM>>>(pxhi, pxlo, prThi, prTlo,
                                           br, pxr, NNODES, HC, HC);
    }

    // CSR by destination
    k_zero_counts<<<(NNODES + 255) / 256, 256>>>();
    k_count<<<(ET + 255) / 256, 256>>>(ei);
    k_scan<<<1, 1024>>>();
    k_scatter<<<(ET + 255) / 256, 256>>>(ei);

    // fused scores + online softmax + aggregation + head mean + bias
    node_fused<<<NNODES, 128>>>(att, bias);

    // fc readout on tensor cores: split hmean, then HMMA GEMM into d_out
    hm_split<<<(NNODES * CH + 255) / 256, 256>>>();
    {
        dim3 grid((NCLS + 127) / 128, (NNODES + 127) / 128);
        gemm_mma<<<grid, 256, GEMM_SMEM>>>(phmhi, phmlo, pfcThi, pfcTlo,
                                           bfc, out, NNODES, NCLS, NCLS);
    }

    // pass-through outputs
    size_t hElems = (size_t)NNODES * NCLS;
    int n4a = in_sizes[10] / 4;
    int n4b = in_sizes[11] / 4;
    k_copy4<<<(n4a + 255) / 256, 256>>>((const float4*)exps,
                                        (float4*)(out + hElems), n4a);
    k_copy4<<<(n4b + 255) / 256, 256>>>((const float4*)exps_c,
                                        (float4*)(out + hElems + in_sizes[10]), n4b);
}